// round 16
// baseline (speedup 1.0000x reference)
#include <cuda_runtime.h>
#include <cuda_fp16.h>
#include <cstdint>

#define M_TOK 8192
#define K_DIM 4096
#define N_OUT 4096
#define NGRP  16
#define KB2   (K_DIM * 2)               // row stride in bytes (fp16)

// ---- scratch (device globals; no allocation allowed) ----
__device__ __align__(16) __half g_a16[(size_t)M_TOK * K_DIM];   // fp16(q - zp), exact ints
__device__ __align__(16) __half g_b16[(size_t)N_OUT * K_DIM];   // fp16((w - z) * s)
__device__ float g_sx[M_TOK];                                    // per-token scale

// ============================================================================
// Fused prep kernel: blocks [0,8192) per-token quant -> g_a16,
//                    blocks [8192,12288) weight dequant -> g_b16
// ============================================================================
__global__ __launch_bounds__(256) void prep_kernel(const float* __restrict__ x,
                                                   const int* __restrict__ W,
                                                   const float* __restrict__ scales,
                                                   const float* __restrict__ zeros) {
    int tid = threadIdx.x;
    if (blockIdx.x < M_TOK) {
        int row = blockIdx.x;
        const float4* xr4 = reinterpret_cast<const float4*>(x + (size_t)row * K_DIM) + tid * 4;

        float4 v[4];
#pragma unroll
        for (int i = 0; i < 4; i++) v[i] = xr4[i];

        float mn = 0.0f, mx = 0.0f;
#pragma unroll
        for (int i = 0; i < 4; i++) {
            mn = fminf(mn, fminf(fminf(v[i].x, v[i].y), fminf(v[i].z, v[i].w)));
            mx = fmaxf(mx, fmaxf(fmaxf(v[i].x, v[i].y), fmaxf(v[i].z, v[i].w)));
        }
#pragma unroll
        for (int off = 16; off; off >>= 1) {
            mn = fminf(mn, __shfl_xor_sync(0xffffffffu, mn, off));
            mx = fmaxf(mx, __shfl_xor_sync(0xffffffffu, mx, off));
        }
        __shared__ float smn[8], smx[8];
        if ((tid & 31) == 0) { smn[tid >> 5] = mn; smx[tid >> 5] = mx; }
        __syncthreads();
        mn = smn[0]; mx = smx[0];
#pragma unroll
        for (int i = 1; i < 8; i++) { mn = fminf(mn, smn[i]); mx = fmaxf(mx, smx[i]); }

        float scale = fmaxf((mx - mn) / 255.0f, 1.1920928955078125e-07f);
        float a = mn / scale, b = mx / scale;
        float t = (-128.0f + a) + (127.0f + b);
        float zp0 = (t > 0.0f) ? (-128.0f - a) : (127.0f - b);
        float zpf = fminf(fmaxf(rintf(zp0), -128.0f), 127.0f);
        float rs = 1.0f / scale;

        const float* pv = reinterpret_cast<const float*>(v);
        uint32_t packed[8];
#pragma unroll
        for (int j = 0; j < 8; j++) {
            float q0 = fminf(fmaxf(rintf(pv[2 * j] * rs) + zpf, -128.0f), 127.0f);
            float q1 = fminf(fmaxf(rintf(pv[2 * j + 1] * rs) + zpf, -128.0f), 127.0f);
            __half2 h = __floats2half2_rn(q0 - zpf, q1 - zpf);   // exact ints in [-255,255]
            packed[j] = *reinterpret_cast<uint32_t*>(&h);
        }
        uint4* dst = reinterpret_cast<uint4*>(g_a16 + (size_t)row * K_DIM + tid * 16);
        dst[0] = make_uint4(packed[0], packed[1], packed[2], packed[3]);
        dst[1] = make_uint4(packed[4], packed[5], packed[6], packed[7]);
        if (tid == 0) g_sx[row] = scale;
    } else {
        int o = blockIdx.x - M_TOK;
        int g = tid >> 4;
        float z = zeros[o * NGRP + g];
        float s = scales[o * NGRP + g];

        const int4* Wrow = reinterpret_cast<const int4*>(W + (size_t)o * K_DIM) + tid * 4;
        uint32_t packed[8];
#pragma unroll
        for (int c = 0; c < 4; c++) {
            int4 w4 = Wrow[c];
            __half2 h0 = __floats2half2_rn(((float)w4.x - z) * s, ((float)w4.y - z) * s);
            __half2 h1 = __floats2half2_rn(((float)w4.z - z) * s, ((float)w4.w - z) * s);
            packed[2 * c]     = *reinterpret_cast<uint32_t*>(&h0);
            packed[2 * c + 1] = *reinterpret_cast<uint32_t*>(&h1);
        }
        uint4* dst = reinterpret_cast<uint4*>(g_b16 + (size_t)o * K_DIM + tid * 16);
        dst[0] = make_uint4(packed[0], packed[1], packed[2], packed[3]);
        dst[1] = make_uint4(packed[4], packed[5], packed[6], packed[7]);
    }
}

// ============================================================================
// GEMM: persistent CTAs, 128x256 tiles, 64x64 warp tiles, 4 stages in PAIRS.
// One bar per 2 stages (8 MMA batches); next pair's 24 chunks spread over
// batches 0-5 at R13's 4-chunks/batch rate; single commit -> wait_group 0.
// ============================================================================
#define BM 128
#define BN 256
#define NSTAGE 4
#define A_TILE (BM * 128)                 // 16384 bytes
#define B_TILE (BN * 128)                 // 32768 bytes
#define STAGE_B (A_TILE + B_TILE)         // 49152
#define SMEM_DYN (NSTAGE * STAGE_B + 1024)
#define KITERS (K_DIM / 64)               // 64 units per tile
#define NSUPER (KITERS / 2)               // 32 super-iterations per tile
#define ROWSTEP (32 * KB2)                // gmem delta per cp.async slice
#define NTILES ((M_TOK / BM) * (N_OUT / BN))   // 1024
#define TPN (N_OUT / BN)                  // 16 tiles along n

__device__ __forceinline__ uint32_t s2u(const void* p) {
    uint32_t a;
    asm("{ .reg .u64 t; cvta.to.shared.u64 t, %1; cvt.u32.u64 %0, t; }" : "=r"(a) : "l"(p));
    return a;
}
__device__ __forceinline__ uint32_t swz(uint32_t r, uint32_t c16) {
    uint32_t off = r * 128 + c16 * 16;
    return off ^ ((off >> 3) & 0x70);
}
__device__ __forceinline__ void ldsm4(uint32_t& d0, uint32_t& d1, uint32_t& d2, uint32_t& d3,
                                      uint32_t addr) {
    asm volatile("ldmatrix.sync.aligned.m8n8.x4.shared.b16 {%0,%1,%2,%3}, [%4];"
                 : "=r"(d0), "=r"(d1), "=r"(d2), "=r"(d3) : "r"(addr));
}
__device__ __forceinline__ void mma_f16(float& c0, float& c1, float& c2, float& c3,
                                        uint32_t a0, uint32_t a1, uint32_t a2, uint32_t a3,
                                        uint32_t b0, uint32_t b1) {
    asm volatile(
        "mma.sync.aligned.m16n8k16.row.col.f32.f16.f16.f32 "
        "{%0,%1,%2,%3}, {%4,%5,%6,%7}, {%8,%9}, {%0,%1,%2,%3};\n"
        : "+f"(c0), "+f"(c1), "+f"(c2), "+f"(c3)
        : "r"(a0), "r"(a1), "r"(a2), "r"(a3), "r"(b0), "r"(b1));
}

__global__ __launch_bounds__(256, 1) void gemm_kernel(float* __restrict__ out) {
    extern __shared__ char smem_raw[];
    char* sm = (char*)(((uintptr_t)smem_raw + 1023) & ~(uintptr_t)1023);
    uint32_t sbase = s2u(sm);

    int tid = threadIdx.x, lane = tid & 31, wid = tid >> 5;
    int warpm = wid & 1, warpn = wid >> 1;        // 2 x 4 warp grid, warp tile 64x64
    int gid = lane >> 2, tig = lane & 3;

    uint32_t aoffb[4], boffb[4];
    {
        int g8 = lane >> 3, rin = lane & 7;
#pragma unroll
        for (int mt = 0; mt < 4; mt++)
            aoffb[mt] = swz(warpm * 64 + mt * 16 + (g8 & 1) * 8 + rin, g8 >> 1);
#pragma unroll
        for (int p = 0; p < 4; p++)
            boffb[p] = A_TILE + swz(warpn * 64 + p * 16 + (g8 >> 1) * 8 + rin, g8 & 1);
    }

    uint32_t sa0 = swz(tid >> 3, tid & 7);
    uint32_t g0  = (uint32_t)((tid >> 3) * KB2 + (tid & 7) * 16);

#define TILE_PTRS(t, A, B)                                                             \
    {                                                                                  \
        A = (const char*)g_a16 + (size_t)((t) / TPN) * BM * KB2;                       \
        B = (const char*)g_b16 + (size_t)((t) % TPN) * BN * KB2;                       \
    }

// full-unit issue (prologue only) with commit; unit kc -> stage kc&3
#define ISSUE_P(Aptr, Bptr, kc)                                                                \
    {                                                                                          \
        uint32_t st = sbase + ((kc) & 3) * STAGE_B + sa0;                                      \
        uint32_t kb = g0 + (kc) * 128;                                                         \
        _Pragma("unroll") for (int i = 0; i < 4; i++)                                          \
            asm volatile("cp.async.cg.shared.global [%0], [%1], 16;"                           \
                         :: "r"(st + i * 4096), "l"((Aptr) + kb + i * ROWSTEP) : "memory");    \
        _Pragma("unroll") for (int i = 0; i < 8; i++)                                          \
            asm volatile("cp.async.cg.shared.global [%0], [%1], 16;"                           \
                         :: "r"(st + A_TILE + i * 4096), "l"((Bptr) + kb + i * ROWSTEP) : "memory"); \
        asm volatile("cp.async.commit_group;" ::: "memory");                                   \
    }

// partial chunk groups (no commit); st includes sa0
#define ISSUE_A4(pp, st, kb)                                                                   \
    if (pf) {                                                                                  \
        _Pragma("unroll") for (int i = 0; i < 4; i++)                                          \
            asm volatile("cp.async.cg.shared.global [%0], [%1], 16;"                           \
                         :: "r"((st) + i * 4096), "l"((pp) + (kb) + i * ROWSTEP) : "memory");  \
    }
#define ISSUE_B4(pp, st, kb, j0)                                                               \
    if (pf) {                                                                                  \
        _Pragma("unroll") for (int i = 0; i < 4; i++)                                          \
            asm volatile("cp.async.cg.shared.global [%0], [%1], 16;"                           \
                         :: "r"((st) + A_TILE + ((j0) + i) * 4096),                            \
                            "l"((pp) + (kb) + ((j0) + i) * ROWSTEP) : "memory");               \
    }

#define LOADFRAG(buf, sA, ks)                                                        \
    {                                                                                \
        _Pragma("unroll") for (int mt = 0; mt < 4; mt++)                             \
            ldsm4(a[buf][mt][0], a[buf][mt][1], a[buf][mt][2], a[buf][mt][3],        \
                  (sA) + (aoffb[mt] ^ ((ks) << 5)));                                 \
        _Pragma("unroll") for (int p = 0; p < 4; p++)                                \
            ldsm4(b[buf][p][0], b[buf][p][1], b[buf][p][2], b[buf][p][3],            \
                  (sA) + (boffb[p] ^ ((ks) << 5)));                                  \
    }

#define MMA_ALL(buf)                                                                         \
    {                                                                                        \
        _Pragma("unroll") for (int mt = 0; mt < 4; mt++)                                     \
            _Pragma("unroll") for (int nt = 0; nt < 8; nt++)                                 \
                mma_f16(c[mt][nt][0], c[mt][nt][1], c[mt][nt][2], c[mt][nt][3],              \
                        a[buf][mt][0], a[buf][mt][1], a[buf][mt][2], a[buf][mt][3],          \
                        b[buf][nt >> 1][(nt & 1) * 2], b[buf][nt >> 1][(nt & 1) * 2 + 1]);   \
    }

    float c[4][8][4];
    uint32_t a[2][4][4], b[2][4][4];

    int t = blockIdx.x;
    if (t >= NTILES) return;
    int tn = t + gridDim.x;
    const char *Ag, *Bg, *nAg, *nBg;
    TILE_PTRS(t, Ag, Bg);
    if (tn < NTILES) TILE_PTRS(tn, nAg, nBg) else { nAg = Ag; nBg = Bg; }

#pragma unroll
    for (int mt = 0; mt < 4; mt++)
#pragma unroll
        for (int nt = 0; nt < 8; nt++)
#pragma unroll
            for (int r = 0; r < 4; r++) c[mt][nt][r] = 0.0f;

    // prologue: fill units 0,1 (stages 0,1); wait both; load unit0 ks0 frags
    ISSUE_P(Ag, Bg, 0); ISSUE_P(Ag, Bg, 1);
    asm volatile("cp.async.wait_group 0;" ::: "memory");
    __syncthreads();
    LOADFRAG(0, sbase, 0);

    while (true) {
        bool has_next = (tn < NTILES);
        for (int j = 0; j < NSUPER; ++j) {
            uint32_t sXr = sbase + ((j & 1) * 2) * STAGE_B;     // read pair
            uint32_t sYr = sXr + STAGE_B;
            uint32_t wX = sbase + (((j & 1) ^ 1) * 2) * STAGE_B + sa0;  // write pair
            uint32_t wY = wX + STAGE_B;

            // prefetch units 2j+2, 2j+3 (may belong to next tile)
            bool pf;
            const char *pA, *pB;
            uint32_t kb0, kb1;
            if (j < NSUPER - 1) {
                pf = true; pA = Ag; pB = Bg;
                kb0 = g0 + (2 * j + 2) * 128; kb1 = kb0 + 128;
            } else if (has_next) {
                pf = true; pA = nAg; pB = nBg;
                kb0 = g0; kb1 = g0 + 128;
            } else {
                pf = false; pA = Ag; pB = Bg; kb0 = g0; kb1 = g0;
            }

            LOADFRAG(1, sXr, 1);  ISSUE_A4(pA, wX, kb0);        MMA_ALL(0);   // X ks0
            LOADFRAG(0, sXr, 2);  ISSUE_B4(pB, wX, kb0, 0);     MMA_ALL(1);   // X ks1
            LOADFRAG(1, sXr, 3);  ISSUE_B4(pB, wX, kb0, 4);     MMA_ALL(0);   // X ks2
            LOADFRAG(0, sYr, 0);  ISSUE_A4(pA, wY, kb1);        MMA_ALL(1);   // X ks3
            LOADFRAG(1, sYr, 1);  ISSUE_B4(pB, wY, kb1, 0);     MMA_ALL(0);   // Y ks0
            LOADFRAG(0, sYr, 2);  ISSUE_B4(pB, wY, kb1, 4);
            if (pf) asm volatile("cp.async.commit_group;" ::: "memory");
            MMA_ALL(1);                                                       // Y ks1
            LOADFRAG(1, sYr, 3);  MMA_ALL(0);                                 // Y ks2
            if (j < NSUPER - 1 || has_next) {
                asm volatile("cp.async.wait_group 0;" ::: "memory");
                __syncthreads();
                LOADFRAG(0, sbase + (((j & 1) ^ 1) * 2) * STAGE_B, 0);        // next X ks0
                MMA_ALL(1);                                                   // Y ks3
            } else {
                MMA_ALL(1);                                                   // Y ks3
            }
        }

        // epilogue for tile t (next tile's units 0,1 already streaming/resident)
        {
            int bm = t / TPN, bn = t % TPN;
#pragma unroll
            for (int mt = 0; mt < 4; ++mt) {
                int rlo = bm * BM + warpm * 64 + mt * 16 + gid;
                int rhi = rlo + 8;
                float sxl = g_sx[rlo];
                float sxh = g_sx[rhi];
#pragma unroll
                for (int nt = 0; nt < 8; ++nt) {
                    int o0 = bn * BN + warpn * 64 + nt * 8 + tig * 2;
                    float2 vlo = make_float2(sxl * c[mt][nt][0], sxl * c[mt][nt][1]);
                    float2 vhi = make_float2(sxh * c[mt][nt][2], sxh * c[mt][nt][3]);
                    *reinterpret_cast<float2*>(out + (size_t)rlo * N_OUT + o0) = vlo;
                    *reinterpret_cast<float2*>(out + (size_t)rhi * N_OUT + o0) = vhi;
                }
            }
        }
        if (!has_next) break;

        t = tn;
        Ag = nAg; Bg = nBg;
        tn = t + gridDim.x;
        if (tn < NTILES) TILE_PTRS(tn, nAg, nBg);
#pragma unroll
        for (int mt = 0; mt < 4; mt++)
#pragma unroll
            for (int nt = 0; nt < 8; nt++)
#pragma unroll
                for (int r = 0; r < 4; r++) c[mt][nt][r] = 0.0f;
    }
}

// ============================================================================
// launch
// ============================================================================
extern "C" void kernel_launch(void* const* d_in, const int* in_sizes, int n_in,
                              void* d_out, int out_size) {
    const float* x      = (const float*)d_in[0];
    const int*   w      = (const int*)d_in[1];     // int8 upcast to int32 by harness
    const float* scales = (const float*)d_in[2];
    const float* zeros  = (const float*)d_in[3];
    float* out = (float*)d_out;

    static int nsm = 0;
    if (nsm == 0) {
        cudaDeviceGetAttribute(&nsm, cudaDevAttrMultiProcessorCount, 0);
        if (nsm <= 0 || nsm > NTILES) nsm = 148;
        cudaFuncSetAttribute(gemm_kernel, cudaFuncAttributeMaxDynamicSharedMemorySize, SMEM_DYN);
    }

    prep_kernel<<<M_TOK + N_OUT, 256>>>(x, w, scales, zeros);
    gemm_kernel<<<nsm, 256, SMEM_DYN>>>(out);
}

// round 17
// speedup vs baseline: 1.0105x; 1.0105x over previous
#include <cuda_runtime.h>
#include <cuda_fp16.h>
#include <cstdint>

#define M_TOK 8192
#define K_DIM 4096
#define N_OUT 4096
#define NGRP  16
#define KB2   (K_DIM * 2)               // row stride in bytes (fp16)

// ---- scratch (device globals; no allocation allowed) ----
__device__ __align__(16) __half g_a16[(size_t)M_TOK * K_DIM];   // fp16(q - zp), exact ints
__device__ __align__(16) __half g_b16[(size_t)N_OUT * K_DIM];   // fp16((w - z) * s)
__device__ float g_sx[M_TOK];                                    // per-token scale

// ============================================================================
// Fused prep kernel: blocks [0,8192) per-token quant -> g_a16,
//                    blocks [8192,12288) weight dequant -> g_b16
// ============================================================================
__global__ __launch_bounds__(256) void prep_kernel(const float* __restrict__ x,
                                                   const int* __restrict__ W,
                                                   const float* __restrict__ scales,
                                                   const float* __restrict__ zeros) {
    int tid = threadIdx.x;
    if (blockIdx.x < M_TOK) {
        int row = blockIdx.x;
        const float4* xr4 = reinterpret_cast<const float4*>(x + (size_t)row * K_DIM) + tid * 4;

        float4 v[4];
#pragma unroll
        for (int i = 0; i < 4; i++) v[i] = xr4[i];

        float mn = 0.0f, mx = 0.0f;
#pragma unroll
        for (int i = 0; i < 4; i++) {
            mn = fminf(mn, fminf(fminf(v[i].x, v[i].y), fminf(v[i].z, v[i].w)));
            mx = fmaxf(mx, fmaxf(fmaxf(v[i].x, v[i].y), fmaxf(v[i].z, v[i].w)));
        }
#pragma unroll
        for (int off = 16; off; off >>= 1) {
            mn = fminf(mn, __shfl_xor_sync(0xffffffffu, mn, off));
            mx = fmaxf(mx, __shfl_xor_sync(0xffffffffu, mx, off));
        }
        __shared__ float smn[8], smx[8];
        if ((tid & 31) == 0) { smn[tid >> 5] = mn; smx[tid >> 5] = mx; }
        __syncthreads();
        mn = smn[0]; mx = smx[0];
#pragma unroll
        for (int i = 1; i < 8; i++) { mn = fminf(mn, smn[i]); mx = fmaxf(mx, smx[i]); }

        float scale = fmaxf((mx - mn) / 255.0f, 1.1920928955078125e-07f);
        float a = mn / scale, b = mx / scale;
        float t = (-128.0f + a) + (127.0f + b);
        float zp0 = (t > 0.0f) ? (-128.0f - a) : (127.0f - b);
        float zpf = fminf(fmaxf(rintf(zp0), -128.0f), 127.0f);
        float rs = 1.0f / scale;    // one IEEE division; per-element FMUL below

        const float* pv = reinterpret_cast<const float*>(v);
        uint32_t packed[8];
#pragma unroll
        for (int j = 0; j < 8; j++) {
            float q0 = fminf(fmaxf(rintf(pv[2 * j] * rs) + zpf, -128.0f), 127.0f);
            float q1 = fminf(fmaxf(rintf(pv[2 * j + 1] * rs) + zpf, -128.0f), 127.0f);
            __half2 h = __floats2half2_rn(q0 - zpf, q1 - zpf);   // exact ints in [-255,255]
            packed[j] = *reinterpret_cast<uint32_t*>(&h);
        }
        uint4* dst = reinterpret_cast<uint4*>(g_a16 + (size_t)row * K_DIM + tid * 16);
        dst[0] = make_uint4(packed[0], packed[1], packed[2], packed[3]);
        dst[1] = make_uint4(packed[4], packed[5], packed[6], packed[7]);
        if (tid == 0) g_sx[row] = scale;
    } else {
        int o = blockIdx.x - M_TOK;
        int g = tid >> 4;
        float z = zeros[o * NGRP + g];
        float s = scales[o * NGRP + g];

        const int4* Wrow = reinterpret_cast<const int4*>(W + (size_t)o * K_DIM) + tid * 4;
        uint32_t packed[8];
#pragma unroll
        for (int c = 0; c < 4; c++) {
            int4 w4 = Wrow[c];
            __half2 h0 = __floats2half2_rn(((float)w4.x - z) * s, ((float)w4.y - z) * s);
            __half2 h1 = __floats2half2_rn(((float)w4.z - z) * s, ((float)w4.w - z) * s);
            packed[2 * c]     = *reinterpret_cast<uint32_t*>(&h0);
            packed[2 * c + 1] = *reinterpret_cast<uint32_t*>(&h1);
        }
        uint4* dst = reinterpret_cast<uint4*>(g_b16 + (size_t)o * K_DIM + tid * 16);
        dst[0] = make_uint4(packed[0], packed[1], packed[2], packed[3]);
        dst[1] = make_uint4(packed[4], packed[5], packed[6], packed[7]);
    }
}

// ============================================================================
// GEMM: persistent CTAs, 128x256 tiles, 64x64 warp tiles, 4-stage cp.async.
// R13 mainloop + pre-bar hoist of next-stage ks0 fragment load (stage kc+1
// was published by the PREVIOUS bar, so reading it pre-bar is legal).
// Post-bar: two full MMA batches with zero ldsm dependency.
// ============================================================================
#define BM 128
#define BN 256
#define NSTAGE 4
#define A_TILE (BM * 128)                 // 16384 bytes
#define B_TILE (BN * 128)                 // 32768 bytes
#define STAGE_B (A_TILE + B_TILE)         // 49152
#define SMEM_DYN (NSTAGE * STAGE_B + 1024)
#define KITERS (K_DIM / 64)               // 64 chunks per tile
#define ROWSTEP (32 * KB2)                // gmem delta per cp.async slice
#define NTILES ((M_TOK / BM) * (N_OUT / BN))   // 1024
#define TPN (N_OUT / BN)                  // 16 tiles along n

__device__ __forceinline__ uint32_t s2u(const void* p) {
    uint32_t a;
    asm("{ .reg .u64 t; cvta.to.shared.u64 t, %1; cvt.u32.u64 %0, t; }" : "=r"(a) : "l"(p));
    return a;
}
__device__ __forceinline__ uint32_t swz(uint32_t r, uint32_t c16) {
    uint32_t off = r * 128 + c16 * 16;
    return off ^ ((off >> 3) & 0x70);
}
__device__ __forceinline__ void ldsm4(uint32_t& d0, uint32_t& d1, uint32_t& d2, uint32_t& d3,
                                      uint32_t addr) {
    asm volatile("ldmatrix.sync.aligned.m8n8.x4.shared.b16 {%0,%1,%2,%3}, [%4];"
                 : "=r"(d0), "=r"(d1), "=r"(d2), "=r"(d3) : "r"(addr));
}
__device__ __forceinline__ void mma_f16(float& c0, float& c1, float& c2, float& c3,
                                        uint32_t a0, uint32_t a1, uint32_t a2, uint32_t a3,
                                        uint32_t b0, uint32_t b1) {
    asm volatile(
        "mma.sync.aligned.m16n8k16.row.col.f32.f16.f16.f32 "
        "{%0,%1,%2,%3}, {%4,%5,%6,%7}, {%8,%9}, {%0,%1,%2,%3};\n"
        : "+f"(c0), "+f"(c1), "+f"(c2), "+f"(c3)
        : "r"(a0), "r"(a1), "r"(a2), "r"(a3), "r"(b0), "r"(b1));
}

__global__ __launch_bounds__(256, 1) void gemm_kernel(float* __restrict__ out) {
    extern __shared__ char smem_raw[];
    char* sm = (char*)(((uintptr_t)smem_raw + 1023) & ~(uintptr_t)1023);
    uint32_t sbase = s2u(sm);

    int tid = threadIdx.x, lane = tid & 31, wid = tid >> 5;
    int warpm = wid & 1, warpn = wid >> 1;        // 2 x 4 warp grid, warp tile 64x64
    int gid = lane >> 2, tig = lane & 3;

    uint32_t aoffb[4], boffb[4];
    {
        int g8 = lane >> 3, rin = lane & 7;
#pragma unroll
        for (int mt = 0; mt < 4; mt++)
            aoffb[mt] = swz(warpm * 64 + mt * 16 + (g8 & 1) * 8 + rin, g8 >> 1);
#pragma unroll
        for (int p = 0; p < 4; p++)
            boffb[p] = A_TILE + swz(warpn * 64 + p * 16 + (g8 >> 1) * 8 + rin, g8 & 1);
    }

    uint32_t sa0 = swz(tid >> 3, tid & 7);
    uint32_t g0  = (uint32_t)((tid >> 3) * KB2 + (tid & 7) * 16);

#define TILE_PTRS(t, A, B)                                                             \
    {                                                                                  \
        A = (const char*)g_a16 + (size_t)((t) / TPN) * BM * KB2;                       \
        B = (const char*)g_b16 + (size_t)((t) % TPN) * BN * KB2;                       \
    }

// full-stage issue (prologue only) with commit
#define ISSUE_P(Aptr, Bptr, kc)                                                                \
    {                                                                                          \
        uint32_t st = sbase + ((kc) & 3) * STAGE_B + sa0;                                      \
        uint32_t kb = g0 + (kc) * 128;                                                         \
        _Pragma("unroll") for (int i = 0; i < 4; i++)                                          \
            asm volatile("cp.async.cg.shared.global [%0], [%1], 16;"                           \
                         :: "r"(st + i * 4096), "l"((Aptr) + kb + i * ROWSTEP) : "memory");    \
        _Pragma("unroll") for (int i = 0; i < 8; i++)                                          \
            asm volatile("cp.async.cg.shared.global [%0], [%1], 16;"                           \
                         :: "r"(st + A_TILE + i * 4096), "l"((Bptr) + kb + i * ROWSTEP) : "memory"); \
        asm volatile("cp.async.commit_group;" ::: "memory");                                   \
    }

// partial slices (no commit)
#define SLICE_A4(pA, pst, pkb)                                                                 \
    if (pf) {                                                                                  \
        _Pragma("unroll") for (int i = 0; i < 4; i++)                                          \
            asm volatile("cp.async.cg.shared.global [%0], [%1], 16;"                           \
                         :: "r"((pst) + i * 4096), "l"((pA) + (pkb) + i * ROWSTEP) : "memory"); \
    }
#define SLICE_B4(pB, pst, pkb, j0)                                                             \
    if (pf) {                                                                                  \
        _Pragma("unroll") for (int i = 0; i < 4; i++)                                          \
            asm volatile("cp.async.cg.shared.global [%0], [%1], 16;"                           \
                         :: "r"((pst) + A_TILE + ((j0) + i) * 4096),                           \
                            "l"((pB) + (pkb) + ((j0) + i) * ROWSTEP) : "memory");              \
    }

#define LOADFRAG(buf, sA, ks)                                                        \
    {                                                                                \
        _Pragma("unroll") for (int mt = 0; mt < 4; mt++)                             \
            ldsm4(a[buf][mt][0], a[buf][mt][1], a[buf][mt][2], a[buf][mt][3],        \
                  (sA) + (aoffb[mt] ^ ((ks) << 5)));                                 \
        _Pragma("unroll") for (int p = 0; p < 4; p++)                                \
            ldsm4(b[buf][p][0], b[buf][p][1], b[buf][p][2], b[buf][p][3],            \
                  (sA) + (boffb[p] ^ ((ks) << 5)));                                  \
    }

#define MMA_ALL(buf)                                                                         \
    {                                                                                        \
        _Pragma("unroll") for (int mt = 0; mt < 4; mt++)                                     \
            _Pragma("unroll") for (int nt = 0; nt < 8; nt++)                                 \
                mma_f16(c[mt][nt][0], c[mt][nt][1], c[mt][nt][2], c[mt][nt][3],              \
                        a[buf][mt][0], a[buf][mt][1], a[buf][mt][2], a[buf][mt][3],          \
                        b[buf][nt >> 1][(nt & 1) * 2], b[buf][nt >> 1][(nt & 1) * 2 + 1]);   \
    }

    float c[4][8][4];
    uint32_t a[2][4][4], b[2][4][4];

    int t = blockIdx.x;
    if (t >= NTILES) return;
    int tn = t + gridDim.x;
    const char *Ag, *Bg, *nAg, *nBg;
    TILE_PTRS(t, Ag, Bg);
    if (tn < NTILES) TILE_PTRS(tn, nAg, nBg) else { nAg = Ag; nBg = Bg; }

#pragma unroll
    for (int mt = 0; mt < 4; mt++)
#pragma unroll
        for (int nt = 0; nt < 8; nt++)
#pragma unroll
            for (int r = 0; r < 4; r++) c[mt][nt][r] = 0.0f;

    // prologue: fill 3 stages; ensure stages 0 AND 1 resident (pre-bar hoist
    // at kc=0 reads stage 1), then load stage-0 ks0 fragments
    ISSUE_P(Ag, Bg, 0); ISSUE_P(Ag, Bg, 1); ISSUE_P(Ag, Bg, 2);
    asm volatile("cp.async.wait_group 1;" ::: "memory");
    __syncthreads();
    LOADFRAG(0, sbase, 0);

    while (true) {
        bool has_next = (tn < NTILES);
        for (int kc = 0; kc < KITERS; ++kc) {
            uint32_t sA = sbase + (kc & 3) * STAGE_B;
            // prefetch target: stage kc+3 (may belong to next tile)
            int nk = kc + 3;
            bool pf;
            const char *pA, *pB;
            uint32_t pst, pkb;
            if (nk < KITERS) {
                pf = true; pA = Ag; pB = Bg;
                pkb = g0 + nk * 128;
            } else if (has_next) {
                pf = true; pA = nAg; pB = nBg;
                pkb = g0 + (nk - KITERS) * 128;
            } else {
                pf = false; pA = Ag; pB = Bg; pkb = g0;
            }
            pst = sbase + (nk & 3) * STAGE_B + sa0;

            LOADFRAG(1, sA, 1);
            SLICE_A4(pA, pst, pkb);
            MMA_ALL(0);                    // ks0
            LOADFRAG(0, sA, 2);
            SLICE_B4(pB, pst, pkb, 0);
            MMA_ALL(1);                    // ks1
            LOADFRAG(1, sA, 3);
            SLICE_B4(pB, pst, pkb, 4);
            MMA_ALL(0);                    // ks2
            if (kc < KITERS - 1 || has_next) {
                // PRE-BAR hoist: stage kc+1 was published by the PREVIOUS bar,
                // so its ks0 fragments are legal to read now (buffer 0 is free
                // once ks2's MMA has issued; WAR handled by scoreboard).
                LOADFRAG(0, sbase + (((kc + 1) & 3) * STAGE_B), 0);
                asm volatile("cp.async.wait_group 1;" ::: "memory");
                __syncthreads();
                asm volatile("cp.async.commit_group;" ::: "memory");
                MMA_ALL(1);                // ks3 — post-bar batch #1 (regs ready)
                                           // next kc's ks0 MMA is batch #2 (regs ready)
            } else {
                MMA_ALL(1);                // ks3
            }
        }

        // epilogue for tile t (next tile's stages stream in meanwhile)
        {
            int bm = t / TPN, bn = t % TPN;
#pragma unroll
            for (int mt = 0; mt < 4; ++mt) {
                int rlo = bm * BM + warpm * 64 + mt * 16 + gid;
                int rhi = rlo + 8;
                float sxl = g_sx[rlo];
                float sxh = g_sx[rhi];
#pragma unroll
                for (int nt = 0; nt < 8; ++nt) {
                    int o0 = bn * BN + warpn * 64 + nt * 8 + tig * 2;
                    float2 vlo = make_float2(sxl * c[mt][nt][0], sxl * c[mt][nt][1]);
                    float2 vhi = make_float2(sxh * c[mt][nt][2], sxh * c[mt][nt][3]);
                    *reinterpret_cast<float2*>(out + (size_t)rlo * N_OUT + o0) = vlo;
                    *reinterpret_cast<float2*>(out + (size_t)rhi * N_OUT + o0) = vhi;
                }
            }
        }
        if (!has_next) break;

        t = tn;
        Ag = nAg; Bg = nBg;
        tn = t + gridDim.x;
        if (tn < NTILES) TILE_PTRS(tn, nAg, nBg);
#pragma unroll
        for (int mt = 0; mt < 4; mt++)
#pragma unroll
            for (int nt = 0; nt < 8; nt++)
#pragma unroll
                for (int r = 0; r < 4; r++) c[mt][nt][r] = 0.0f;
    }
}

// ============================================================================
// launch
// ============================================================================
extern "C" void kernel_launch(void* const* d_in, const int* in_sizes, int n_in,
                              void* d_out, int out_size) {
    const float* x      = (const float*)d_in[0];
    const int*   w      = (const int*)d_in[1];     // int8 upcast to int32 by harness
    const float* scales = (const float*)d_in[2];
    const float* zeros  = (const float*)d_in[3];
    float* out = (float*)d_out;

    static int nsm = 0;
    if (nsm == 0) {
        cudaDeviceGetAttribute(&nsm, cudaDevAttrMultiProcessorCount, 0);
        if (nsm <= 0 || nsm > NTILES) nsm = 148;
        cudaFuncSetAttribute(gemm_kernel, cudaFuncAttributeMaxDynamicSharedMemorySize, SMEM_DYN);
    }

    prep_kernel<<<M_TOK + N_OUT, 256>>>(x, w, scales, zeros);
    gemm_kernel<<<nsm, 256, SMEM_DYN>>>(out);
}